// round 2
// baseline (speedup 1.0000x reference)
#include <cuda_runtime.h>
#include <math.h>

#define MM   16          // B*T
#define NN   5000
#define DIN  64
#define EE   80000
#define HC   128
#define E2   (EE + NN)   // 85000 with self loops
#define ROWS (MM * NN)   // 80000

// ---------------- scratch (no allocations allowed) ----------------
// ALL feature buffers are (m,n)-major: row = m*NN + n  (matches x and d_out layouts)
__device__ float g_xl[ROWS * HC];   // 41 MB
__device__ float g_xr[ROWS * HC];
__device__ float g_h [ROWS * HC];   // layer-1 output
__device__ int   g_cnt[NN];
__device__ float g_wsum[NN];
__device__ int   g_rowoff[NN + 1];
__device__ int   g_fill[NN];
__device__ float g_selfw[NN];
__device__ int2  g_epk[E2];         // {src, bitcast(weight)}

// ---------------- preprocessing ----------------
__global__ void k_zero() {
    int i = blockIdx.x * blockDim.x + threadIdx.x;
    if (i < NN) { g_cnt[i] = 0; g_wsum[i] = 0.f; }
}

__global__ void k_deg(const int* __restrict__ ei, const float* __restrict__ ew) {
    int e = blockIdx.x * blockDim.x + threadIdx.x;
    if (e < EE) {
        int d = __ldg(&ei[EE + e]);
        atomicAdd(&g_cnt[d], 1);
        atomicAdd(&g_wsum[d], __ldg(&ew[e]));
    }
}

// one block, 1024 threads: exclusive scan of (deg+1), self-loop weights
__global__ void k_scan() {
    __shared__ int sums[1024];
    int tid = threadIdx.x;
    int base = tid * 5;
    int loc[5];
    int s = 0;
#pragma unroll
    for (int j = 0; j < 5; j++) {
        int i = base + j;
        int d = (i < NN) ? (g_cnt[i] + 1) : 0;   // +1 for self loop
        loc[j] = s;
        s += d;
    }
    sums[tid] = s;
    __syncthreads();
    for (int off = 1; off < 1024; off <<= 1) {
        int v = (tid >= off) ? sums[tid - off] : 0;
        __syncthreads();
        sums[tid] += v;
        __syncthreads();
    }
    int excl = (tid == 0) ? 0 : sums[tid - 1];
#pragma unroll
    for (int j = 0; j < 5; j++) {
        int i = base + j;
        if (i < NN) {
            int o = excl + loc[j];
            g_rowoff[i] = o;
            g_fill[i]   = o;
            int c = g_cnt[i];
            g_selfw[i] = (c > 0) ? (g_wsum[i] / (float)c) : 0.f;
        }
    }
    if (tid == 1023) g_rowoff[NN] = sums[1023];
}

__global__ void k_scatter(const int* __restrict__ ei, const float* __restrict__ ew) {
    int i = blockIdx.x * blockDim.x + threadIdx.x;
    if (i < EE) {
        int d = ei[EE + i];
        int p = atomicAdd(&g_fill[d], 1);
        g_epk[p] = make_int2(ei[i], __float_as_int(ew[i]));
    } else if (i < E2) {
        int n = i - EE;
        int p = atomicAdd(&g_fill[n], 1);
        g_epk[p] = make_int2(n, __float_as_int(g_selfw[n]));
    }
}

// ---------------- projections: xl = A@Wl, xr = A@Wr ----------------
// 128x128 block tile, 256 threads, 8x8 microtile, K-chunk 16, register
// prefetch of next chunk overlapped with compute. blockIdx.y: 0 -> Wl/g_xl,
// 1 -> Wr/g_xr. IN_H selects g_h as the input matrix.
template <int K, int IN_H>
__global__ void __launch_bounds__(256) k_gemm(const float* __restrict__ Ain,
                                              const float* __restrict__ Wl,
                                              const float* __restrict__ Wr) {
    __shared__ float As[16][128];
    __shared__ float Bs[16][128];

    const float* __restrict__ A = IN_H ? (const float*)g_h : Ain;
    const float* __restrict__ W = blockIdx.y ? Wr : Wl;
    float* __restrict__ dst     = blockIdx.y ? g_xr : g_xl;

    const int tid  = threadIdx.x;
    const int row0 = blockIdx.x * 128;

    // A staging: thread covers row r, k-sub kq*8..kq*8+7
    const int ar = tid & 127;
    const int kq = tid >> 7;                 // 0..1
    const float* Ap = A + (size_t)(row0 + ar) * K + kq * 8;
    // B staging: two float4 rows
    const int bk = tid >> 5;                 // 0..7
    const int bc = (tid & 31) * 4;
    const float* Wp0 = W + bk * 128 + bc;
    const float* Wp1 = W + (bk + 8) * 128 + bc;

    const int tr = tid >> 4;                 // 0..15 -> rows tr*8..
    const int tc = tid & 15;                 // 0..15 -> cols tc*8..

    float acc[8][8];
#pragma unroll
    for (int i = 0; i < 8; i++)
#pragma unroll
        for (int j = 0; j < 8; j++) acc[i][j] = 0.f;

    constexpr int NC = K / 16;
    float4 va0 = *(const float4*)(Ap);
    float4 va1 = *(const float4*)(Ap + 4);
    float4 vb0 = *(const float4*)(Wp0);
    float4 vb1 = *(const float4*)(Wp1);

#pragma unroll
    for (int c = 0; c < NC; c++) {
        // stage registers -> smem
        As[kq * 8 + 0][ar] = va0.x;  As[kq * 8 + 1][ar] = va0.y;
        As[kq * 8 + 2][ar] = va0.z;  As[kq * 8 + 3][ar] = va0.w;
        As[kq * 8 + 4][ar] = va1.x;  As[kq * 8 + 5][ar] = va1.y;
        As[kq * 8 + 6][ar] = va1.z;  As[kq * 8 + 7][ar] = va1.w;
        *(float4*)&Bs[bk][bc]     = vb0;
        *(float4*)&Bs[bk + 8][bc] = vb1;
        __syncthreads();

        // prefetch next chunk (hidden under compute below)
        if (c + 1 < NC) {
            va0 = *(const float4*)(Ap + (c + 1) * 16);
            va1 = *(const float4*)(Ap + (c + 1) * 16 + 4);
            vb0 = *(const float4*)(Wp0 + (c + 1) * 16 * 128);
            vb1 = *(const float4*)(Wp1 + (c + 1) * 16 * 128);
        }

#pragma unroll
        for (int k = 0; k < 16; k++) {
            float a[8], b[8];
            *(float4*)&a[0] = *(const float4*)&As[k][tr * 8];
            *(float4*)&a[4] = *(const float4*)&As[k][tr * 8 + 4];
            *(float4*)&b[0] = *(const float4*)&Bs[k][tc * 8];
            *(float4*)&b[4] = *(const float4*)&Bs[k][tc * 8 + 4];
#pragma unroll
            for (int i = 0; i < 8; i++)
#pragma unroll
                for (int j = 0; j < 8; j++) acc[i][j] = fmaf(a[i], b[j], acc[i][j]);
        }
        __syncthreads();
    }

    // coalesced epilogue: rows stay (m,n)-major
#pragma unroll
    for (int i = 0; i < 8; i++) {
        float* o = dst + (size_t)(row0 + tr * 8 + i) * HC + tc * 8;
        *(float4*)o       = make_float4(acc[i][0], acc[i][1], acc[i][2], acc[i][3]);
        *(float4*)(o + 4) = make_float4(acc[i][4], acc[i][5], acc[i][6], acc[i][7]);
    }
}

// ---------------- fused edge kernel: gather + online softmax + aggregate ----------------
// one warp per (dst, m). lane owns channels 4*lane..4*lane+3; lanes 0-15 head 0,
// lanes 16-31 head 1. Software-pipelined: edge j+1's xj load issued before edge
// j's shuffle/exp chain. LAYER2 writes ELU(out) to d_out, else to g_h.
template <int LAYER2>
__global__ void __launch_bounds__(256) k_edge(const float* __restrict__ We,
                                              const float* __restrict__ att,
                                              const float* __restrict__ bias,
                                              float* __restrict__ out) {
    const int warp = threadIdx.x >> 5;
    const int lane = threadIdx.x & 31;
    const int dst  = blockIdx.x >> 1;
    const int m    = ((blockIdx.x & 1) << 3) | warp;
    const int mbase = m * NN;

    float4 xi = *(const float4*)&g_xr[(size_t)(mbase + dst) * HC + lane * 4];
    float4 we = *(const float4*)&We[lane * 4];
    float4 at = *(const float4*)&att[lane * 4];

    float ax = 0.f, ay = 0.f, az = 0.f, aw = 0.f;
    float mx = -1e30f, dn = 0.f;

    const int beg = g_rowoff[dst];
    const int end = g_rowoff[dst + 1];   // always >= beg+1 (self loop)

    int2 ep = g_epk[beg];
    float  w  = __int_as_float(ep.y);
    float4 xj = *(const float4*)&g_xl[(size_t)(mbase + ep.x) * HC + lane * 4];

    for (int j = beg; j < end; j++) {
        float4 xjc = xj;
        float  wc  = w;
        if (j + 1 < end) {
            int2 e2 = g_epk[j + 1];
            w  = __int_as_float(e2.y);
            xj = *(const float4*)&g_xl[(size_t)(mbase + e2.x) * HC + lane * 4];
        }

        float t0 = xi.x + xjc.x + wc * we.x;
        float t1 = xi.y + xjc.y + wc * we.y;
        float t2 = xi.z + xjc.z + wc * we.z;
        float t3 = xi.w + xjc.w + wc * we.w;
        t0 = (t0 > 0.f) ? t0 : 0.2f * t0;
        t1 = (t1 > 0.f) ? t1 : 0.2f * t1;
        t2 = (t2 > 0.f) ? t2 : 0.2f * t2;
        t3 = (t3 > 0.f) ? t3 : 0.2f * t3;
        float p = t0 * at.x;
        p = fmaf(t1, at.y, p);
        p = fmaf(t2, at.z, p);
        p = fmaf(t3, at.w, p);
        // half-warp (per-head) reduction
        p += __shfl_xor_sync(0xffffffffu, p, 1);
        p += __shfl_xor_sync(0xffffffffu, p, 2);
        p += __shfl_xor_sync(0xffffffffu, p, 4);
        p += __shfl_xor_sync(0xffffffffu, p, 8);

        float nm = fmaxf(mx, p);
        float sc = __expf(mx - nm);
        float e  = __expf(p - nm);
        dn = dn * sc + e;
        ax = fmaf(e, xjc.x, ax * sc);
        ay = fmaf(e, xjc.y, ay * sc);
        az = fmaf(e, xjc.z, az * sc);
        aw = fmaf(e, xjc.w, aw * sc);
        mx = nm;
    }

    float inv = 1.f / (dn + 1e-16f);
    float4 b  = *(const float4*)&bias[lane * 4];
    float o0 = ax * inv + b.x;
    float o1 = ay * inv + b.y;
    float o2 = az * inv + b.z;
    float o3 = aw * inv + b.w;
    // ELU epilogue (both layers are followed by ELU in the reference)
    o0 = (o0 > 0.f) ? o0 : (__expf(o0) - 1.f);
    o1 = (o1 > 0.f) ? o1 : (__expf(o1) - 1.f);
    o2 = (o2 > 0.f) ? o2 : (__expf(o2) - 1.f);
    o3 = (o3 > 0.f) ? o3 : (__expf(o3) - 1.f);

    float* dstp = LAYER2 ? (out + (size_t)(mbase + dst) * HC + lane * 4)
                         : (g_h + (size_t)(mbase + dst) * HC + lane * 4);
    *(float4*)dstp = make_float4(o0, o1, o2, o3);
}

// ---------------- launch ----------------
extern "C" void kernel_launch(void* const* d_in, const int* in_sizes, int n_in,
                              void* d_out, int out_size) {
    const float* x    = (const float*)d_in[0];
    const int*   ei   = (const int*)d_in[1];
    const float* ew   = (const float*)d_in[2];
    const float* Wl1  = (const float*)d_in[3];
    const float* Wr1  = (const float*)d_in[4];
    const float* att1 = (const float*)d_in[5];
    const float* We1  = (const float*)d_in[6];
    const float* b1   = (const float*)d_in[7];
    const float* Wl2  = (const float*)d_in[8];
    const float* Wr2  = (const float*)d_in[9];
    const float* att2 = (const float*)d_in[10];
    const float* We2  = (const float*)d_in[11];
    const float* b2   = (const float*)d_in[12];
    float* out = (float*)d_out;

    k_zero<<<(NN + 255) / 256, 256>>>();
    k_deg<<<(EE + 255) / 256, 256>>>(ei, ew);
    k_scan<<<1, 1024>>>();
    k_scatter<<<(E2 + 255) / 256, 256>>>(ei, ew);

    dim3 gg(ROWS / 128, 2);
    // layer 1
    k_gemm<DIN, 0><<<gg, 256>>>(x, Wl1, Wr1);
    k_edge<0><<<NN * 2, 256>>>(We1, att1, b1, nullptr);
    // layer 2
    k_gemm<HC, 1><<<gg, 256>>>(nullptr, Wl2, Wr2);
    k_edge<1><<<NN * 2, 256>>>(We2, att2, b2, out);
}

// round 4
// speedup vs baseline: 1.5631x; 1.5631x over previous
#include <cuda_runtime.h>
#include <cstdint>
#include <math.h>

#define MM   16          // B*T
#define NN   5000
#define DIN  64
#define EE   80000
#define HC   128
#define E2   (EE + NN)   // 85000 with self loops
#define ROWS (MM * NN)   // 80000

// ---------------- scratch (no allocations allowed) ----------------
// feature buffers are NODE-major: row = n*MM + m (proven best for the gather)
__device__ float g_xl[ROWS * HC];   // 41 MB
__device__ float g_xr[ROWS * HC];
__device__ float g_h [ROWS * HC];   // layer-1 output (node-major)
__device__ int   g_cnt[NN];
__device__ float g_wsum[NN];
__device__ int   g_rowoff[NN + 1];
__device__ int   g_fill[NN];
__device__ float g_selfw[NN];
__device__ int2  g_epk[E2];         // {src, bitcast(weight)}

// ---------------- preprocessing ----------------
__global__ void k_zero() {
    int i = blockIdx.x * blockDim.x + threadIdx.x;
    if (i < NN) { g_cnt[i] = 0; g_wsum[i] = 0.f; }
}

__global__ void k_deg(const int* __restrict__ ei, const float* __restrict__ ew) {
    int e = blockIdx.x * blockDim.x + threadIdx.x;
    if (e < EE) {
        int d = __ldg(&ei[EE + e]);
        atomicAdd(&g_cnt[d], 1);
        atomicAdd(&g_wsum[d], __ldg(&ew[e]));
    }
}

// one block, 1024 threads: exclusive scan of (deg+1), self-loop weights
__global__ void k_scan() {
    __shared__ int sums[1024];
    int tid = threadIdx.x;
    int base = tid * 5;
    int loc[5];
    int s = 0;
#pragma unroll
    for (int j = 0; j < 5; j++) {
        int i = base + j;
        int d = (i < NN) ? (g_cnt[i] + 1) : 0;   // +1 for self loop
        loc[j] = s;
        s += d;
    }
    sums[tid] = s;
    __syncthreads();
    for (int off = 1; off < 1024; off <<= 1) {
        int v = (tid >= off) ? sums[tid - off] : 0;
        __syncthreads();
        sums[tid] += v;
        __syncthreads();
    }
    int excl = (tid == 0) ? 0 : sums[tid - 1];
#pragma unroll
    for (int j = 0; j < 5; j++) {
        int i = base + j;
        if (i < NN) {
            int o = excl + loc[j];
            g_rowoff[i] = o;
            g_fill[i]   = o;
            int c = g_cnt[i];
            g_selfw[i] = (c > 0) ? (g_wsum[i] / (float)c) : 0.f;
        }
    }
    if (tid == 1023) g_rowoff[NN] = sums[1023];
}

__global__ void k_scatter(const int* __restrict__ ei, const float* __restrict__ ew) {
    int i = blockIdx.x * blockDim.x + threadIdx.x;
    if (i < EE) {
        int d = ei[EE + i];
        int p = atomicAdd(&g_fill[d], 1);
        g_epk[p] = make_int2(ei[i], __float_as_int(ew[i]));
    } else if (i < E2) {
        int n = i - EE;
        int p = atomicAdd(&g_fill[n], 1);
        g_epk[p] = make_int2(n, __float_as_int(g_selfw[n]));
    }
}

// ---------------- cp.async helpers ----------------
__device__ __forceinline__ void cpa16(unsigned int d, const float* s) {
    asm volatile("cp.async.ca.shared.global [%0], [%1], 16;" :: "r"(d), "l"(s));
}

// ---------------- projections: [xl | xr] = A @ [Wl | Wr] ----------------
// 64 rows x 256 cols tile, 256 threads, 8x8 microtile, K-chunk 32,
// double-buffered cp.async pipeline (dynamic smem 80KB, 2 CTAs/SM).
// smem layout (floats): As0 [0,2048) As1 [2048,4096) Bs0 [4096,12288) Bs1 [12288,20480)
// As layout: [row][k] (64x32), Bs layout: [k][col] (32x256).
// MAP==1: A rows are (m*NN+n) (raw x) -> output row n*MM+m. IN_H: read g_h.
template <int K, int MAP, int IN_H>
__global__ void __launch_bounds__(256) k_gemm(const float* __restrict__ Ain,
                                              const float* __restrict__ Wl,
                                              const float* __restrict__ Wr) {
    extern __shared__ float sm[];
    const float* __restrict__ A = IN_H ? (const float*)g_h : Ain;

    const int tid  = threadIdx.x;
    const int row0 = blockIdx.x * 64;
    const unsigned int sbase = (unsigned int)__cvta_generic_to_shared(sm);

    // staging maps
    const int ar = tid >> 3;          // 0..31 used twice -> rows 0..63
    const int aq = (tid & 7) * 4;     // k-offset (floats)
    const int bk = tid >> 6;          // 0..3, +4 steps of 4 -> k 0..31
    const int bc = (tid & 63) * 4;    // col*4 over 256

    auto issue = [&](int c, int buf) {
        unsigned int as = sbase + (buf ? 2048u * 4u : 0u);
        const float* Ab = A + (size_t)row0 * K + c * 32;
#pragma unroll
        for (int i = 0; i < 2; i++) {
            int r = ar + i * 32;
            cpa16(as + (unsigned int)(r * 32 + aq) * 4u, Ab + (size_t)r * K + aq);
        }
        unsigned int bs = sbase + (4096u + (buf ? 8192u : 0u)) * 4u;
#pragma unroll
        for (int i = 0; i < 8; i++) {
            int k = bk + i * 4;
            const float* src = (bc < 128) ? (Wl + (size_t)(c * 32 + k) * 128 + bc)
                                          : (Wr + (size_t)(c * 32 + k) * 128 + (bc - 128));
            cpa16(bs + (unsigned int)(k * 256 + bc) * 4u, src);
        }
        asm volatile("cp.async.commit_group;" ::: "memory");
    };

    constexpr int NC = K / 32;
    issue(0, 0);
    if (NC > 1) issue(1, 1);

    const int tr = tid >> 5;          // warp id -> rows tr*8..
    const int tc = tid & 31;          // cols tc*8.. of 256

    float acc[8][8];
#pragma unroll
    for (int i = 0; i < 8; i++)
#pragma unroll
        for (int j = 0; j < 8; j++) acc[i][j] = 0.f;

#pragma unroll
    for (int c = 0; c < NC; c++) {
        if (c + 1 < NC) asm volatile("cp.async.wait_group 1;" ::: "memory");
        else            asm volatile("cp.async.wait_group 0;" ::: "memory");
        __syncthreads();

        const float* Ab = sm + (c & 1 ? 2048 : 0);
        const float* Bb = sm + 4096 + (c & 1 ? 8192 : 0);
#pragma unroll
        for (int k = 0; k < 32; k++) {
            float a[8], b[8];
#pragma unroll
            for (int i = 0; i < 8; i++) a[i] = Ab[(tr * 8 + i) * 32 + k];  // broadcast
            *(float4*)&b[0] = *(const float4*)&Bb[k * 256 + tc * 8];
            *(float4*)&b[4] = *(const float4*)&Bb[k * 256 + tc * 8 + 4];
#pragma unroll
            for (int i = 0; i < 8; i++)
#pragma unroll
                for (int j = 0; j < 8; j++) acc[i][j] = fmaf(a[i], b[j], acc[i][j]);
        }
        __syncthreads();
        if (c + 2 < NC) issue(c + 2, c & 1);
    }

    // epilogue: warp writes contiguous 512B row-halves (coalesced even with MAP)
    int cnum = tc * 8;
    float* dstbuf = (cnum < 128) ? g_xl : g_xr;
    int cc = (cnum < 128) ? cnum : (cnum - 128);
#pragma unroll
    for (int i = 0; i < 8; i++) {
        int r = row0 + tr * 8 + i;
        int orow;
        if (MAP == 1) {
            int m = r / NN;
            int n = r - m * NN;
            orow  = n * MM + m;
        } else {
            orow = r;
        }
        float* o = dstbuf + (size_t)orow * HC + cc;
        *(float4*)o       = make_float4(acc[i][0], acc[i][1], acc[i][2], acc[i][3]);
        *(float4*)(o + 4) = make_float4(acc[i][4], acc[i][5], acc[i][6], acc[i][7]);
    }
}

// ---------------- fused edge kernel: gather + online softmax + aggregate ----------------
// one warp per (dst, m). lane owns channels 4*lane..4*lane+3; lanes 0-15 head 0,
// 16-31 head 1. Next edge's xj prefetched before this edge's shuffle/exp chain.
template <int LAYER2>
__global__ void __launch_bounds__(256) k_edge(const float* __restrict__ We,
                                              const float* __restrict__ att,
                                              const float* __restrict__ bias,
                                              float* __restrict__ out) {
    const int warp = threadIdx.x >> 5;
    const int lane = threadIdx.x & 31;
    const int dst  = blockIdx.x >> 1;
    const int m    = ((blockIdx.x & 1) << 3) | warp;

    float4 xi = *(const float4*)&g_xr[(size_t)(dst * MM + m) * HC + lane * 4];
    float4 we = *(const float4*)&We[lane * 4];
    float4 at = *(const float4*)&att[lane * 4];

    float ax = 0.f, ay = 0.f, az = 0.f, aw = 0.f;
    float mx = -1e30f, dn = 0.f;

    const int beg = __ldg(&g_rowoff[dst]);
    const int end = __ldg(&g_rowoff[dst + 1]);   // >= beg+1 (self loop)

    int2 ep = g_epk[beg];
    float  w  = __int_as_float(ep.y);
    float4 xj = *(const float4*)&g_xl[(size_t)(ep.x * MM + m) * HC + lane * 4];

    for (int j = beg; j < end; j++) {
        float4 xjc = xj;
        float  wc  = w;
        if (j + 1 < end) {
            int2 e2 = g_epk[j + 1];
            w  = __int_as_float(e2.y);
            xj = *(const float4*)&g_xl[(size_t)(e2.x * MM + m) * HC + lane * 4];
        }

        float t0 = xi.x + xjc.x + wc * we.x;
        float t1 = xi.y + xjc.y + wc * we.y;
        float t2 = xi.z + xjc.z + wc * we.z;
        float t3 = xi.w + xjc.w + wc * we.w;
        t0 = (t0 > 0.f) ? t0 : 0.2f * t0;
        t1 = (t1 > 0.f) ? t1 : 0.2f * t1;
        t2 = (t2 > 0.f) ? t2 : 0.2f * t2;
        t3 = (t3 > 0.f) ? t3 : 0.2f * t3;
        float p = t0 * at.x;
        p = fmaf(t1, at.y, p);
        p = fmaf(t2, at.z, p);
        p = fmaf(t3, at.w, p);
        // half-warp (per-head) reduction
        p += __shfl_xor_sync(0xffffffffu, p, 1);
        p += __shfl_xor_sync(0xffffffffu, p, 2);
        p += __shfl_xor_sync(0xffffffffu, p, 4);
        p += __shfl_xor_sync(0xffffffffu, p, 8);

        float nm = fmaxf(mx, p);
        float sc = __expf(mx - nm);
        float e  = __expf(p - nm);
        dn = dn * sc + e;
        ax = fmaf(e, xjc.x, ax * sc);
        ay = fmaf(e, xjc.y, ay * sc);
        az = fmaf(e, xjc.z, az * sc);
        aw = fmaf(e, xjc.w, aw * sc);
        mx = nm;
    }

    float inv = 1.f / (dn + 1e-16f);
    float4 b  = *(const float4*)&bias[lane * 4];
    float o0 = ax * inv + b.x;
    float o1 = ay * inv + b.y;
    float o2 = az * inv + b.z;
    float o3 = aw * inv + b.w;
    // ELU epilogue (both layers are followed by ELU in the reference)
    o0 = (o0 > 0.f) ? o0 : (__expf(o0) - 1.f);
    o1 = (o1 > 0.f) ? o1 : (__expf(o1) - 1.f);
    o2 = (o2 > 0.f) ? o2 : (__expf(o2) - 1.f);
    o3 = (o3 > 0.f) ? o3 : (__expf(o3) - 1.f);

    if (LAYER2) {
        *(float4*)&out[(size_t)(m * NN + dst) * HC + lane * 4] = make_float4(o0, o1, o2, o3);
    } else {
        *(float4*)&g_h[(size_t)(dst * MM + m) * HC + lane * 4] = make_float4(o0, o1, o2, o3);
    }
}

// ---------------- launch ----------------
extern "C" void kernel_launch(void* const* d_in, const int* in_sizes, int n_in,
                              void* d_out, int out_size) {
    const float* x    = (const float*)d_in[0];
    const int*   ei   = (const int*)d_in[1];
    const float* ew   = (const float*)d_in[2];
    const float* Wl1  = (const float*)d_in[3];
    const float* Wr1  = (const float*)d_in[4];
    const float* att1 = (const float*)d_in[5];
    const float* We1  = (const float*)d_in[6];
    const float* b1   = (const float*)d_in[7];
    const float* Wl2  = (const float*)d_in[8];
    const float* Wr2  = (const float*)d_in[9];
    const float* att2 = (const float*)d_in[10];
    const float* We2  = (const float*)d_in[11];
    const float* b2   = (const float*)d_in[12];
    float* out = (float*)d_out;

    const int smem = 20480 * 4;   // 80KB dynamic
    static int configured = 0;
    cudaFuncSetAttribute(k_gemm<DIN, 1, 0>, cudaFuncAttributeMaxDynamicSharedMemorySize, smem);
    cudaFuncSetAttribute(k_gemm<HC, 0, 1>, cudaFuncAttributeMaxDynamicSharedMemorySize, smem);
    (void)configured;

    k_zero<<<(NN + 255) / 256, 256>>>();
    k_deg<<<(EE + 255) / 256, 256>>>(ei, ew);
    k_scan<<<1, 1024>>>();
    k_scatter<<<(E2 + 255) / 256, 256>>>(ei, ew);

    // layer 1
    k_gemm<DIN, 1, 0><<<ROWS / 64, 256, smem>>>(x, Wl1, Wr1);
    k_edge<0><<<NN * 2, 256>>>(We1, att1, b1, nullptr);
    // layer 2
    k_gemm<HC, 0, 1><<<ROWS / 64, 256, smem>>>(nullptr, Wl2, Wr2);
    k_edge<1><<<NN * 2, 256>>>(We2, att2, b2, out);
}